// round 8
// baseline (speedup 1.0000x reference)
#include <cuda_runtime.h>
#include <cuda_bf16.h>

#define N_NODES 50000
#define N_EDGES 800000
#define NFEAT 128
#define NHID 128
#define NOUT 64

// ---------------- scratch (static __device__, no allocations) ----------------
__device__ __align__(16) __nv_bfloat16 g_support[N_NODES * 128];  // bf16 support
__device__ __align__(16) float g_h[N_NODES * 128];
__device__ int   g_rowptr[N_NODES + 1];
__device__ int   g_cursor[N_NODES];
__device__ int   g_blocksum[128];
__device__ __align__(16) int g_csr_ew[N_EDGES * 2];   // interleaved {src, w_bits}

// ---------------- helpers ----------------
__device__ __forceinline__ void ffma2(unsigned long long& d,
                                      unsigned long long a,
                                      unsigned long long b) {
    asm("fma.rn.f32x2 %0, %1, %2, %0;" : "+l"(d) : "l"(a), "l"(b));
}
__device__ __forceinline__ unsigned long long dup2(float x) {
    unsigned long long r;
    asm("mov.b64 %0, {%1, %1};" : "=l"(r) : "f"(x));
    return r;
}
__device__ __forceinline__ unsigned cvt_bf2(unsigned long long pair) {
    float lo, hi; unsigned r;
    asm("mov.b64 {%0, %1}, %2;" : "=f"(lo), "=f"(hi) : "l"(pair));
    asm("cvt.rn.bf16x2.f32 %0, %1, %2;" : "=r"(r) : "f"(hi), "f"(lo));
    return r;
}
__device__ __forceinline__ float2 bf2f(unsigned bits) {
    __nv_bfloat162 h = *reinterpret_cast<const __nv_bfloat162*>(&bits);
    return __bfloat1622float2(h);
}

// ---------------- CSR build ----------------
__global__ void zero_cursor_kernel() {
    int i = blockIdx.x * blockDim.x + threadIdx.x;
    if (i < N_NODES) g_cursor[i] = 0;
}

__global__ void hist_kernel(const int* __restrict__ dst) {
    int e = blockIdx.x * blockDim.x + threadIdx.x;
    if (e < N_EDGES) atomicAdd(&g_cursor[dst[e]], 1);
}

__global__ void scan_blocks_kernel() {
    __shared__ int sdata[512];
    const int tid = threadIdx.x;
    int i = blockIdx.x * 512 + tid;
    int v = (i < N_NODES) ? g_cursor[i] : 0;
    sdata[tid] = v;
    __syncthreads();
#pragma unroll
    for (int off = 1; off < 512; off <<= 1) {
        int t = (tid >= off) ? sdata[tid - off] : 0;
        __syncthreads();
        sdata[tid] += t;
        __syncthreads();
    }
    if (i < N_NODES) g_rowptr[i] = sdata[tid] - v;
    if (tid == 511) g_blocksum[blockIdx.x] = sdata[511];
}

__global__ void scan_tops_kernel(int nblk) {
    __shared__ int sdata[128];
    const int tid = threadIdx.x;
    int v = (tid < nblk) ? g_blocksum[tid] : 0;
    sdata[tid] = v;
    __syncthreads();
#pragma unroll
    for (int off = 1; off < 128; off <<= 1) {
        int t = (tid >= off) ? sdata[tid - off] : 0;
        __syncthreads();
        sdata[tid] += t;
        __syncthreads();
    }
    if (tid < nblk) g_blocksum[tid] = sdata[tid] - v;
}

__global__ void add_offsets_kernel() {
    int i = blockIdx.x * 512 + threadIdx.x;
    if (i < N_NODES) {
        g_rowptr[i] += g_blocksum[blockIdx.x];
        g_cursor[i] = 0;
    }
    if (i == 0) g_rowptr[N_NODES] = N_EDGES;
}

__global__ void scatter_kernel(const int* __restrict__ src,
                               const int* __restrict__ dst,
                               const float* __restrict__ w) {
    int e = blockIdx.x * blockDim.x + threadIdx.x;
    if (e < N_EDGES) {
        int d = dst[e];
        int pos = g_rowptr[d] + atomicAdd(&g_cursor[d], 1);
        reinterpret_cast<int2*>(g_csr_ew)[pos] =
            make_int2(src[e], __float_as_int(w[e]));
    }
}

// ---------------- dense GEMM: C[M,BN](bf16) = A[M,128](f32) @ B[128,BN](f32)
// BM=128, BK=16, double-buffered smem (48 KB), 256 threads, FFMA2 math,
// bf16x2 epilogue. (unchanged from R7 — at FFMA2 issue floor)
template <int BN>
__global__ void __launch_bounds__(256)
gemm_kernel(const float* __restrict__ A, const float* __restrict__ B,
            __nv_bfloat16* __restrict__ C, int M) {
    constexpr int K = 128, BM = 128, BK = 16;
    constexpr int TM = 8, TN = BN / 16, TN2 = TN / 2;
    constexpr int NSLAB = K / BK;                 // 8
    constexpr int A_IT = (BM * BK / 4) / 256;     // 2
    constexpr int B_IT = (BK * BN / 4) / 256;     // 2 (BN=128) / 1 (BN=64)

    __shared__ unsigned long long As2[2][BK][BM]; // 2 x 16 KB, {a,a} pairs
    __shared__ float Bs[2][BK][BN];               // 2 x 8/4 KB

    const int tid = threadIdx.x;
    const int m0  = blockIdx.x * BM;
    const int tx  = tid % 16;
    const int ty  = tid / 16;
    const int mm  = ty * TM;
    const int nn  = tx * TN;

    unsigned long long acc2[TM][TN2];
#pragma unroll
    for (int i = 0; i < TM; i++)
#pragma unroll
        for (int j = 0; j < TN2; j++) acc2[i][j] = 0ull;

    const float4* A4 = reinterpret_cast<const float4*>(A);
    const float4* B4 = reinterpret_cast<const float4*>(B);

    float4 areg[A_IT], breg[B_IT];

    auto load_global = [&](int s) {
#pragma unroll
        for (int it = 0; it < A_IT; it++) {
            int f  = tid + it * 256;
            int m  = f & (BM - 1);
            int kq = f >> 7;                       // 0..BK/4-1
            int gm = m0 + m;
            areg[it] = (gm < M) ? A4[gm * (K / 4) + (s * BK) / 4 + kq]
                                : make_float4(0.f, 0.f, 0.f, 0.f);
        }
#pragma unroll
        for (int it = 0; it < B_IT; it++) {
            int f = tid + it * 256;
            breg[it] = B4[(s * BK) * (BN / 4) + f];
        }
    };
    auto store_smem = [&](int buf) {
#pragma unroll
        for (int it = 0; it < A_IT; it++) {
            int f  = tid + it * 256;
            int m  = f & (BM - 1);
            int k  = (f >> 7) * 4;
            As2[buf][k + 0][m] = dup2(areg[it].x);
            As2[buf][k + 1][m] = dup2(areg[it].y);
            As2[buf][k + 2][m] = dup2(areg[it].z);
            As2[buf][k + 3][m] = dup2(areg[it].w);
        }
#pragma unroll
        for (int it = 0; it < B_IT; it++) {
            int f = tid + it * 256;
            reinterpret_cast<float4*>(&Bs[buf][0][0])[f] = breg[it];
        }
    };
    auto compute = [&](int buf) {
#pragma unroll
        for (int k = 0; k < BK; k++) {
            unsigned long long a2[TM];
#pragma unroll
            for (int i2 = 0; i2 < TM / 2; i2++) {
                ulonglong2 av = *reinterpret_cast<const ulonglong2*>(&As2[buf][k][mm + i2 * 2]);
                a2[i2 * 2 + 0] = av.x;
                a2[i2 * 2 + 1] = av.y;
            }
            unsigned long long b2[TN2];
#pragma unroll
            for (int j4 = 0; j4 < TN2 / 2; j4++) {
                ulonglong2 bv = *reinterpret_cast<const ulonglong2*>(&Bs[buf][k][nn + j4 * 4]);
                b2[j4 * 2 + 0] = bv.x;
                b2[j4 * 2 + 1] = bv.y;
            }
#pragma unroll
            for (int i = 0; i < TM; i++)
#pragma unroll
                for (int j = 0; j < TN2; j++) ffma2(acc2[i][j], a2[i], b2[j]);
        }
    };

    load_global(0);
    store_smem(0);
    __syncthreads();

    for (int s = 0; s < NSLAB; s++) {
        int cur = s & 1;
        bool has_next = (s + 1) < NSLAB;
        if (has_next) load_global(s + 1);   // LDG latency hidden by compute
        compute(cur);
        if (has_next) store_smem(cur ^ 1);
        __syncthreads();
    }

    // epilogue: pack each f32 pair -> bf16x2, vector store
#pragma unroll
    for (int i = 0; i < TM; i++) {
        int row = m0 + mm + i;
        if (row < M) {
            unsigned r32[TN2];
#pragma unroll
            for (int j = 0; j < TN2; j++) r32[j] = cvt_bf2(acc2[i][j]);
            unsigned* outp = reinterpret_cast<unsigned*>(C + row * BN + nn);
            if constexpr (TN2 == 4) {
                uint4 o = make_uint4(r32[0], r32[1], r32[2], r32[3]);
                *reinterpret_cast<uint4*>(outp) = o;
            } else {
                uint2 o = make_uint2(r32[0], r32[1]);
                *reinterpret_cast<uint2*>(outp) = o;
            }
        }
    }
}

// ---------------- SpMM (CSR-by-dst, bf16 gather, packed edges) ----------------
// one warp per destination node; lane owns D/32 consecutive channels.
// Edge stream is {src, w} int2 pairs -> two edges per broadcast LDG.128.
template <int D, bool RELU>
__global__ void spmm_kernel(const __nv_bfloat16* __restrict__ sup,
                            const float* __restrict__ bias,
                            float* __restrict__ out) {
    int gw = (blockIdx.x * blockDim.x + threadIdx.x) >> 5;
    if (gw >= N_NODES) return;
    int lane = threadIdx.x & 31;
    int s = g_rowptr[gw];
    int e = g_rowptr[gw + 1];

    const int4* ew4 = reinterpret_cast<const int4*>(g_csr_ew);  // 2 edges each
    const int2* ew2 = reinterpret_cast<const int2*>(g_csr_ew);  // 1 edge each

    if constexpr (D == 128) {
        const uint2* supv = reinterpret_cast<const uint2*>(sup);  // 32 uint2/row
        float4 acc = make_float4(0.f, 0.f, 0.f, 0.f);
        int i = s;

        auto edge = [&](int sn, float wn) {
            uint2 v = supv[sn * 32 + lane];
            float2 p;
            p = bf2f(v.x); acc.x += wn * p.x; acc.y += wn * p.y;
            p = bf2f(v.y); acc.z += wn * p.x; acc.w += wn * p.y;
        };

        if (i < e && (i & 1)) {               // align to int4 boundary
            int2 p = ew2[i];
            edge(p.x, __int_as_float(p.y));
            i++;
        }
        for (; i + 3 < e; i += 4) {           // 4 edges: 2 LDG.128 + 4 gathers
            int4 pa = ew4[i >> 1];
            int4 pb = ew4[(i >> 1) + 1];
            uint2 v0 = supv[pa.x * 32 + lane];
            uint2 v1 = supv[pa.z * 32 + lane];
            uint2 v2 = supv[pb.x * 32 + lane];
            uint2 v3 = supv[pb.z * 32 + lane];
            float w0 = __int_as_float(pa.y), w1 = __int_as_float(pa.w);
            float w2 = __int_as_float(pb.y), w3 = __int_as_float(pb.w);
            float2 p;
            p = bf2f(v0.x); acc.x += w0 * p.x; acc.y += w0 * p.y;
            p = bf2f(v0.y); acc.z += w0 * p.x; acc.w += w0 * p.y;
            p = bf2f(v1.x); acc.x += w1 * p.x; acc.y += w1 * p.y;
            p = bf2f(v1.y); acc.z += w1 * p.x; acc.w += w1 * p.y;
            p = bf2f(v2.x); acc.x += w2 * p.x; acc.y += w2 * p.y;
            p = bf2f(v2.y); acc.z += w2 * p.x; acc.w += w2 * p.y;
            p = bf2f(v3.x); acc.x += w3 * p.x; acc.y += w3 * p.y;
            p = bf2f(v3.y); acc.z += w3 * p.x; acc.w += w3 * p.y;
        }
        for (; i + 1 < e; i += 2) {
            int4 pa = ew4[i >> 1];
            edge(pa.x, __int_as_float(pa.y));
            edge(pa.z, __int_as_float(pa.w));
        }
        if (i < e) {
            int2 p = ew2[i];
            edge(p.x, __int_as_float(p.y));
        }

        float4 b = reinterpret_cast<const float4*>(bias)[lane];
        acc.x += b.x; acc.y += b.y; acc.z += b.z; acc.w += b.w;
        if (RELU) {
            acc.x = fmaxf(acc.x, 0.f); acc.y = fmaxf(acc.y, 0.f);
            acc.z = fmaxf(acc.z, 0.f); acc.w = fmaxf(acc.w, 0.f);
        }
        reinterpret_cast<float4*>(out)[gw * 32 + lane] = acc;
    } else {  // D == 64
        const unsigned* supv = reinterpret_cast<const unsigned*>(sup);  // 32 u32/row
        float2 acc = make_float2(0.f, 0.f);
        int i = s;

        auto edge = [&](int sn, float wn) {
            float2 p = bf2f(supv[sn * 32 + lane]);
            acc.x += wn * p.x; acc.y += wn * p.y;
        };

        if (i < e && (i & 1)) {
            int2 p = ew2[i];
            edge(p.x, __int_as_float(p.y));
            i++;
        }
        for (; i + 3 < e; i += 4) {
            int4 pa = ew4[i >> 1];
            int4 pb = ew4[(i >> 1) + 1];
            unsigned v0 = supv[pa.x * 32 + lane];
            unsigned v1 = supv[pa.z * 32 + lane];
            unsigned v2 = supv[pb.x * 32 + lane];
            unsigned v3 = supv[pb.z * 32 + lane];
            float w0 = __int_as_float(pa.y), w1 = __int_as_float(pa.w);
            float w2 = __int_as_float(pb.y), w3 = __int_as_float(pb.w);
            float2 p;
            p = bf2f(v0); acc.x += w0 * p.x; acc.y += w0 * p.y;
            p = bf2f(v1); acc.x += w1 * p.x; acc.y += w1 * p.y;
            p = bf2f(v2); acc.x += w2 * p.x; acc.y += w2 * p.y;
            p = bf2f(v3); acc.x += w3 * p.x; acc.y += w3 * p.y;
        }
        for (; i + 1 < e; i += 2) {
            int4 pa = ew4[i >> 1];
            edge(pa.x, __int_as_float(pa.y));
            edge(pa.z, __int_as_float(pa.w));
        }
        if (i < e) {
            int2 p = ew2[i];
            edge(p.x, __int_as_float(p.y));
        }

        float2 b = reinterpret_cast<const float2*>(bias)[lane];
        acc.x += b.x; acc.y += b.y;
        if (RELU) { acc.x = fmaxf(acc.x, 0.f); acc.y = fmaxf(acc.y, 0.f); }
        reinterpret_cast<float2*>(out)[gw * 32 + lane] = acc;
    }
}

// ---------------- launch ----------------
extern "C" void kernel_launch(void* const* d_in, const int* in_sizes, int n_in,
                              void* d_out, int out_size) {
    const float* x        = (const float*)d_in[0];
    const int*   edge_src = (const int*)  d_in[1];
    const int*   edge_dst = (const int*)  d_in[2];
    const float* edge_w   = (const float*)d_in[3];
    const float* W0 = (const float*)d_in[4];  const float* b0 = (const float*)d_in[5];
    const float* W1 = (const float*)d_in[6];  const float* b1 = (const float*)d_in[7];
    const float* W2 = (const float*)d_in[8];  const float* b2 = (const float*)d_in[9];
    const float* W3 = (const float*)d_in[10]; const float* b3 = (const float*)d_in[11];
    float* out = (float*)d_out;

    __nv_bfloat16* support; cudaGetSymbolAddress((void**)&support, g_support);
    float* h;               cudaGetSymbolAddress((void**)&h, g_h);

    const int NB_NODE = (N_NODES + 255) / 256;
    const int NB_EDGE = (N_EDGES + 255) / 256;
    const int NB_GEMM = (N_NODES + 127) / 128;
    const int NB_SPMM = (N_NODES + 7) / 8;      // 8 warps/block
    const int NB_SCAN = (N_NODES + 511) / 512;  // 98

    // fork: CSR build on a side stream, concurrent with gemm0 (independent).
    // kernel_launch is called exactly twice (correctness + capture), so the
    // per-call stream/event creation is bounded and never freed (no device mem).
    cudaStream_t s_side;
    cudaEvent_t  ev_fork, ev_join;
    cudaStreamCreateWithFlags(&s_side, cudaStreamNonBlocking);
    cudaEventCreateWithFlags(&ev_fork, cudaEventDisableTiming);
    cudaEventCreateWithFlags(&ev_join, cudaEventDisableTiming);

    cudaEventRecord(ev_fork, 0);
    cudaStreamWaitEvent(s_side, ev_fork, 0);

    // CSR build on side stream
    zero_cursor_kernel<<<NB_NODE, 256, 0, s_side>>>();
    hist_kernel<<<NB_EDGE, 256, 0, s_side>>>(edge_dst);
    scan_blocks_kernel<<<NB_SCAN, 512, 0, s_side>>>();
    scan_tops_kernel<<<1, 128, 0, s_side>>>(NB_SCAN);
    add_offsets_kernel<<<NB_SCAN, 512, 0, s_side>>>();  // also re-zeros cursor
    scatter_kernel<<<NB_EDGE, 256, 0, s_side>>>(edge_src, edge_dst, edge_w);
    cudaEventRecord(ev_join, s_side);

    // layer 0 GEMM on main stream, concurrent with CSR build
    gemm_kernel<128><<<NB_GEMM, 256>>>(x, W0, support, N_NODES);

    cudaStreamWaitEvent(0, ev_join, 0);   // join before first SpMM

    spmm_kernel<128, true><<<NB_SPMM, 256>>>(support, b0, h);
    // layer 1
    gemm_kernel<128><<<NB_GEMM, 256>>>(h, W1, support, N_NODES);
    spmm_kernel<128, true><<<NB_SPMM, 256>>>(support, b1, h);
    // layer 2
    gemm_kernel<128><<<NB_GEMM, 256>>>(h, W2, support, N_NODES);
    spmm_kernel<128, true><<<NB_SPMM, 256>>>(support, b2, h);
    // layer 3 (d=64, no relu) -> d_out
    gemm_kernel<64><<<NB_GEMM, 256>>>(h, W3, support, N_NODES);
    spmm_kernel<64, false><<<NB_SPMM, 256>>>(support, b3, out);
}

// round 9
// speedup vs baseline: 1.5057x; 1.5057x over previous
#include <cuda_runtime.h>
#include <cuda_bf16.h>

#define N_NODES 50000
#define N_EDGES 800000
#define NFEAT 128
#define NHID 128
#define NOUT 64

// ---------------- scratch (static __device__, no allocations) ----------------
__device__ __align__(16) __nv_bfloat16 g_support[N_NODES * 128];  // bf16 support
__device__ __align__(16) float g_h[N_NODES * 128];
__device__ int   g_rowptr[N_NODES + 1];
__device__ int   g_cursor[N_NODES];
__device__ int   g_blocksum[128];
__device__ __align__(16) int g_csr_ew[N_EDGES * 2];   // interleaved {src, w_bits}

// ---------------- helpers ----------------
__device__ __forceinline__ void ffma2(unsigned long long& d,
                                      unsigned long long a,
                                      unsigned long long b) {
    asm("fma.rn.f32x2 %0, %1, %2, %0;" : "+l"(d) : "l"(a), "l"(b));
}
__device__ __forceinline__ unsigned long long dup2(float x) {
    unsigned long long r;
    asm("mov.b64 %0, {%1, %1};" : "=l"(r) : "f"(x));
    return r;
}
__device__ __forceinline__ unsigned cvt_bf2(unsigned long long pair) {
    float lo, hi; unsigned r;
    asm("mov.b64 {%0, %1}, %2;" : "=f"(lo), "=f"(hi) : "l"(pair));
    asm("cvt.rn.bf16x2.f32 %0, %1, %2;" : "=r"(r) : "f"(hi), "f"(lo));
    return r;
}
__device__ __forceinline__ float2 bf2f(unsigned bits) {
    __nv_bfloat162 h = *reinterpret_cast<const __nv_bfloat162*>(&bits);
    return __bfloat1622float2(h);
}

// ---------------- CSR build ----------------
__global__ void hist_kernel(const int* __restrict__ dst) {
    int e = blockIdx.x * blockDim.x + threadIdx.x;
    if (e < N_EDGES) atomicAdd(&g_cursor[dst[e]], 1);
}

__global__ void scan_blocks_kernel() {
    __shared__ int sdata[512];
    const int tid = threadIdx.x;
    int i = blockIdx.x * 512 + tid;
    int v = (i < N_NODES) ? g_cursor[i] : 0;
    sdata[tid] = v;
    __syncthreads();
#pragma unroll
    for (int off = 1; off < 512; off <<= 1) {
        int t = (tid >= off) ? sdata[tid - off] : 0;
        __syncthreads();
        sdata[tid] += t;
        __syncthreads();
    }
    if (i < N_NODES) g_rowptr[i] = sdata[tid] - v;
    if (tid == 511) g_blocksum[blockIdx.x] = sdata[511];
}

__global__ void scan_tops_kernel(int nblk) {
    __shared__ int sdata[128];
    const int tid = threadIdx.x;
    int v = (tid < nblk) ? g_blocksum[tid] : 0;
    sdata[tid] = v;
    __syncthreads();
#pragma unroll
    for (int off = 1; off < 128; off <<= 1) {
        int t = (tid >= off) ? sdata[tid - off] : 0;
        __syncthreads();
        sdata[tid] += t;
        __syncthreads();
    }
    if (tid < nblk) g_blocksum[tid] = sdata[tid] - v;
}

__global__ void add_offsets_kernel() {
    int i = blockIdx.x * 512 + threadIdx.x;
    if (i < N_NODES) {
        g_rowptr[i] += g_blocksum[blockIdx.x];
        g_cursor[i] = 0;      // re-zero for scatter pass
    }
    if (i == 0) g_rowptr[N_NODES] = N_EDGES;
}

__global__ void scatter_kernel(const int* __restrict__ src,
                               const int* __restrict__ dst,
                               const float* __restrict__ w) {
    int e = blockIdx.x * blockDim.x + threadIdx.x;
    if (e < N_EDGES) {
        int d = dst[e];
        int pos = g_rowptr[d] + atomicAdd(&g_cursor[d], 1);
        reinterpret_cast<int2*>(g_csr_ew)[pos] =
            make_int2(src[e], __float_as_int(w[e]));
    }
}

// ---------------- dense GEMM: C[M,BN](bf16) = A[M,128](f32) @ B[128,BN](f32)
// BM=128, BK=16, double-buffered smem (48 KB), 256 threads, FFMA2 math,
// bf16x2 epilogue.
template <int BN>
__global__ void __launch_bounds__(256)
gemm_kernel(const float* __restrict__ A, const float* __restrict__ B,
            __nv_bfloat16* __restrict__ C, int M) {
    constexpr int K = 128, BM = 128, BK = 16;
    constexpr int TM = 8, TN = BN / 16, TN2 = TN / 2;
    constexpr int NSLAB = K / BK;                 // 8
    constexpr int A_IT = (BM * BK / 4) / 256;     // 2
    constexpr int B_IT = (BK * BN / 4) / 256;     // 2 (BN=128) / 1 (BN=64)

    __shared__ unsigned long long As2[2][BK][BM]; // 2 x 16 KB, {a,a} pairs
    __shared__ float Bs[2][BK][BN];               // 2 x 8/4 KB

    const int tid = threadIdx.x;
    const int m0  = blockIdx.x * BM;
    const int tx  = tid % 16;
    const int ty  = tid / 16;
    const int mm  = ty * TM;
    const int nn  = tx * TN;

    unsigned long long acc2[TM][TN2];
#pragma unroll
    for (int i = 0; i < TM; i++)
#pragma unroll
        for (int j = 0; j < TN2; j++) acc2[i][j] = 0ull;

    const float4* A4 = reinterpret_cast<const float4*>(A);
    const float4* B4 = reinterpret_cast<const float4*>(B);

    float4 areg[A_IT], breg[B_IT];

    auto load_global = [&](int s) {
#pragma unroll
        for (int it = 0; it < A_IT; it++) {
            int f  = tid + it * 256;
            int m  = f & (BM - 1);
            int kq = f >> 7;                       // 0..BK/4-1
            int gm = m0 + m;
            areg[it] = (gm < M) ? A4[gm * (K / 4) + (s * BK) / 4 + kq]
                                : make_float4(0.f, 0.f, 0.f, 0.f);
        }
#pragma unroll
        for (int it = 0; it < B_IT; it++) {
            int f = tid + it * 256;
            breg[it] = B4[(s * BK) * (BN / 4) + f];
        }
    };
    auto store_smem = [&](int buf) {
#pragma unroll
        for (int it = 0; it < A_IT; it++) {
            int f  = tid + it * 256;
            int m  = f & (BM - 1);
            int k  = (f >> 7) * 4;
            As2[buf][k + 0][m] = dup2(areg[it].x);
            As2[buf][k + 1][m] = dup2(areg[it].y);
            As2[buf][k + 2][m] = dup2(areg[it].z);
            As2[buf][k + 3][m] = dup2(areg[it].w);
        }
#pragma unroll
        for (int it = 0; it < B_IT; it++) {
            int f = tid + it * 256;
            reinterpret_cast<float4*>(&Bs[buf][0][0])[f] = breg[it];
        }
    };
    auto compute = [&](int buf) {
#pragma unroll
        for (int k = 0; k < BK; k++) {
            unsigned long long a2[TM];
#pragma unroll
            for (int i2 = 0; i2 < TM / 2; i2++) {
                ulonglong2 av = *reinterpret_cast<const ulonglong2*>(&As2[buf][k][mm + i2 * 2]);
                a2[i2 * 2 + 0] = av.x;
                a2[i2 * 2 + 1] = av.y;
            }
            unsigned long long b2[TN2];
#pragma unroll
            for (int j4 = 0; j4 < TN2 / 2; j4++) {
                ulonglong2 bv = *reinterpret_cast<const ulonglong2*>(&Bs[buf][k][nn + j4 * 4]);
                b2[j4 * 2 + 0] = bv.x;
                b2[j4 * 2 + 1] = bv.y;
            }
#pragma unroll
            for (int i = 0; i < TM; i++)
#pragma unroll
                for (int j = 0; j < TN2; j++) ffma2(acc2[i][j], a2[i], b2[j]);
        }
    };

    load_global(0);
    store_smem(0);
    __syncthreads();

    for (int s = 0; s < NSLAB; s++) {
        int cur = s & 1;
        bool has_next = (s + 1) < NSLAB;
        if (has_next) load_global(s + 1);   // LDG latency hidden by compute
        compute(cur);
        if (has_next) store_smem(cur ^ 1);
        __syncthreads();
    }

    // epilogue: pack each f32 pair -> bf16x2, vector store
#pragma unroll
    for (int i = 0; i < TM; i++) {
        int row = m0 + mm + i;
        if (row < M) {
            unsigned r32[TN2];
#pragma unroll
            for (int j = 0; j < TN2; j++) r32[j] = cvt_bf2(acc2[i][j]);
            unsigned* outp = reinterpret_cast<unsigned*>(C + row * BN + nn);
            if constexpr (TN2 == 4) {
                uint4 o = make_uint4(r32[0], r32[1], r32[2], r32[3]);
                *reinterpret_cast<uint4*>(outp) = o;
            } else {
                uint2 o = make_uint2(r32[0], r32[1]);
                *reinterpret_cast<uint2*>(outp) = o;
            }
        }
    }
}

// ---------------- SpMM (CSR-by-dst, bf16 gather, packed edges) ----------------
// one warp per destination node; lane owns D/32 consecutive channels.
// Edge stream is {src, w} int2 pairs -> two edges per broadcast LDG.128.
template <int D, bool RELU>
__global__ void spmm_kernel(const __nv_bfloat16* __restrict__ sup,
                            const float* __restrict__ bias,
                            float* __restrict__ out) {
    int gw = (blockIdx.x * blockDim.x + threadIdx.x) >> 5;
    if (gw >= N_NODES) return;
    int lane = threadIdx.x & 31;
    int s = g_rowptr[gw];
    int e = g_rowptr[gw + 1];

    const int4* ew4 = reinterpret_cast<const int4*>(g_csr_ew);  // 2 edges each
    const int2* ew2 = reinterpret_cast<const int2*>(g_csr_ew);  // 1 edge each

    if constexpr (D == 128) {
        const uint2* supv = reinterpret_cast<const uint2*>(sup);  // 32 uint2/row
        float4 acc = make_float4(0.f, 0.f, 0.f, 0.f);
        int i = s;

        auto edge = [&](int sn, float wn) {
            uint2 v = supv[sn * 32 + lane];
            float2 p;
            p = bf2f(v.x); acc.x += wn * p.x; acc.y += wn * p.y;
            p = bf2f(v.y); acc.z += wn * p.x; acc.w += wn * p.y;
        };

        if (i < e && (i & 1)) {               // align to int4 boundary
            int2 p = ew2[i];
            edge(p.x, __int_as_float(p.y));
            i++;
        }
        for (; i + 3 < e; i += 4) {           // 4 edges: 2 LDG.128 + 4 gathers
            int4 pa = ew4[i >> 1];
            int4 pb = ew4[(i >> 1) + 1];
            uint2 v0 = supv[pa.x * 32 + lane];
            uint2 v1 = supv[pa.z * 32 + lane];
            uint2 v2 = supv[pb.x * 32 + lane];
            uint2 v3 = supv[pb.z * 32 + lane];
            float w0 = __int_as_float(pa.y), w1 = __int_as_float(pa.w);
            float w2 = __int_as_float(pb.y), w3 = __int_as_float(pb.w);
            float2 p;
            p = bf2f(v0.x); acc.x += w0 * p.x; acc.y += w0 * p.y;
            p = bf2f(v0.y); acc.z += w0 * p.x; acc.w += w0 * p.y;
            p = bf2f(v1.x); acc.x += w1 * p.x; acc.y += w1 * p.y;
            p = bf2f(v1.y); acc.z += w1 * p.x; acc.w += w1 * p.y;
            p = bf2f(v2.x); acc.x += w2 * p.x; acc.y += w2 * p.y;
            p = bf2f(v2.y); acc.z += w2 * p.x; acc.w += w2 * p.y;
            p = bf2f(v3.x); acc.x += w3 * p.x; acc.y += w3 * p.y;
            p = bf2f(v3.y); acc.z += w3 * p.x; acc.w += w3 * p.y;
        }
        for (; i + 1 < e; i += 2) {
            int4 pa = ew4[i >> 1];
            edge(pa.x, __int_as_float(pa.y));
            edge(pa.z, __int_as_float(pa.w));
        }
        if (i < e) {
            int2 p = ew2[i];
            edge(p.x, __int_as_float(p.y));
        }

        float4 b = reinterpret_cast<const float4*>(bias)[lane];
        acc.x += b.x; acc.y += b.y; acc.z += b.z; acc.w += b.w;
        if (RELU) {
            acc.x = fmaxf(acc.x, 0.f); acc.y = fmaxf(acc.y, 0.f);
            acc.z = fmaxf(acc.z, 0.f); acc.w = fmaxf(acc.w, 0.f);
        }
        reinterpret_cast<float4*>(out)[gw * 32 + lane] = acc;
    } else {  // D == 64
        const unsigned* supv = reinterpret_cast<const unsigned*>(sup);  // 32 u32/row
        float2 acc = make_float2(0.f, 0.f);
        int i = s;

        auto edge = [&](int sn, float wn) {
            float2 p = bf2f(supv[sn * 32 + lane]);
            acc.x += wn * p.x; acc.y += wn * p.y;
        };

        if (i < e && (i & 1)) {
            int2 p = ew2[i];
            edge(p.x, __int_as_float(p.y));
            i++;
        }
        for (; i + 3 < e; i += 4) {
            int4 pa = ew4[i >> 1];
            int4 pb = ew4[(i >> 1) + 1];
            unsigned v0 = supv[pa.x * 32 + lane];
            unsigned v1 = supv[pa.z * 32 + lane];
            unsigned v2 = supv[pb.x * 32 + lane];
            unsigned v3 = supv[pb.z * 32 + lane];
            float w0 = __int_as_float(pa.y), w1 = __int_as_float(pa.w);
            float w2 = __int_as_float(pb.y), w3 = __int_as_float(pb.w);
            float2 p;
            p = bf2f(v0); acc.x += w0 * p.x; acc.y += w0 * p.y;
            p = bf2f(v1); acc.x += w1 * p.x; acc.y += w1 * p.y;
            p = bf2f(v2); acc.x += w2 * p.x; acc.y += w2 * p.y;
            p = bf2f(v3); acc.x += w3 * p.x; acc.y += w3 * p.y;
        }
        for (; i + 1 < e; i += 2) {
            int4 pa = ew4[i >> 1];
            edge(pa.x, __int_as_float(pa.y));
            edge(pa.z, __int_as_float(pa.w));
        }
        if (i < e) {
            int2 p = ew2[i];
            edge(p.x, __int_as_float(p.y));
        }

        float2 b = reinterpret_cast<const float2*>(bias)[lane];
        acc.x += b.x; acc.y += b.y;
        if (RELU) { acc.x = fmaxf(acc.x, 0.f); acc.y = fmaxf(acc.y, 0.f); }
        reinterpret_cast<float2*>(out)[gw * 32 + lane] = acc;
    }
}

// ---------------- launch (single stream — R7 topology) ----------------
extern "C" void kernel_launch(void* const* d_in, const int* in_sizes, int n_in,
                              void* d_out, int out_size) {
    const float* x        = (const float*)d_in[0];
    const int*   edge_src = (const int*)  d_in[1];
    const int*   edge_dst = (const int*)  d_in[2];
    const float* edge_w   = (const float*)d_in[3];
    const float* W0 = (const float*)d_in[4];  const float* b0 = (const float*)d_in[5];
    const float* W1 = (const float*)d_in[6];  const float* b1 = (const float*)d_in[7];
    const float* W2 = (const float*)d_in[8];  const float* b2 = (const float*)d_in[9];
    const float* W3 = (const float*)d_in[10]; const float* b3 = (const float*)d_in[11];
    float* out = (float*)d_out;

    __nv_bfloat16* support; cudaGetSymbolAddress((void**)&support, g_support);
    float* h;               cudaGetSymbolAddress((void**)&h, g_h);
    int*   cursor;          cudaGetSymbolAddress((void**)&cursor, g_cursor);

    const int NB_EDGE = (N_EDGES + 255) / 256;
    const int NB_GEMM = (N_NODES + 127) / 128;
    const int NB_SPMM = (N_NODES + 7) / 8;      // 8 warps/block
    const int NB_SCAN = (N_NODES + 511) / 512;  // 98

    // CSR build (single stream; graph-capturable memset replaces zero kernel)
    cudaMemsetAsync(cursor, 0, N_NODES * sizeof(int), 0);
    hist_kernel<<<NB_EDGE, 256>>>(edge_dst);
    scan_blocks_kernel<<<NB_SCAN, 512>>>();
    scan_tops_kernel<<<1, 128>>>(NB_SCAN);
    add_offsets_kernel<<<NB_SCAN, 512>>>();     // also re-zeros cursor
    scatter_kernel<<<NB_EDGE, 256>>>(edge_src, edge_dst, edge_w);

    // layer 0: x -> h
    gemm_kernel<128><<<NB_GEMM, 256>>>(x, W0, support, N_NODES);
    spmm_kernel<128, true><<<NB_SPMM, 256>>>(support, b0, h);
    // layer 1
    gemm_kernel<128><<<NB_GEMM, 256>>>(h, W1, support, N_NODES);
    spmm_kernel<128, true><<<NB_SPMM, 256>>>(support, b1, h);
    // layer 2
    gemm_kernel<128><<<NB_GEMM, 256>>>(h, W2, support, N_NODES);
    spmm_kernel<128, true><<<NB_SPMM, 256>>>(support, b2, h);
    // layer 3 (d=64, no relu) -> d_out
    gemm_kernel<64><<<NB_GEMM, 256>>>(h, W3, support, N_NODES);
    spmm_kernel<64, false><<<NB_SPMM, 256>>>(support, b3, out);
}

// round 10
// speedup vs baseline: 1.5625x; 1.0378x over previous
#include <cuda_runtime.h>
#include <cuda_bf16.h>

#define N_NODES 50000
#define N_EDGES 800000
#define NFEAT 128
#define NHID 128
#define NOUT 64

#define NB_GEMM_C ((N_NODES + 127) / 128)     // 391
#define NB_EDGE_C ((N_EDGES + 255) / 256)     // 3125
#define NBLK_SCAN ((N_NODES + 511) / 512)     // 98

// ---------------- scratch (static __device__, no allocations) ----------------
__device__ __align__(16) __nv_bfloat16 g_support[N_NODES * 128];  // bf16 support
__device__ __align__(16) float g_h[N_NODES * 128];
__device__ int   g_rowptr[N_NODES + 1];       // chunk-LOCAL exclusive prefix
__device__ int   g_cursor[N_NODES];
__device__ int   g_blocksum[128];             // exclusive chunk offsets
__device__ int   g_scan_done;
__device__ __align__(16) int g_csr_ew[N_EDGES * 2];   // interleaved {src, w_bits}

// ---------------- helpers ----------------
__device__ __forceinline__ void ffma2(unsigned long long& d,
                                      unsigned long long a,
                                      unsigned long long b) {
    asm("fma.rn.f32x2 %0, %1, %2, %0;" : "+l"(d) : "l"(a), "l"(b));
}
__device__ __forceinline__ unsigned long long dup2(float x) {
    unsigned long long r;
    asm("mov.b64 %0, {%1, %1};" : "=l"(r) : "f"(x));
    return r;
}
__device__ __forceinline__ unsigned cvt_bf2(unsigned long long pair) {
    float lo, hi; unsigned r;
    asm("mov.b64 {%0, %1}, %2;" : "=f"(lo), "=f"(hi) : "l"(pair));
    asm("cvt.rn.bf16x2.f32 %0, %1, %2;" : "=r"(r) : "f"(hi), "f"(lo));
    return r;
}
__device__ __forceinline__ float2 bf2f(unsigned bits) {
    __nv_bfloat162 h = *reinterpret_cast<const __nv_bfloat162*>(&bits);
    return __bfloat1622float2(h);
}

// ---------------- GEMM body: C[M,BN](bf16) = A[M,128](f32) @ B[128,BN](f32)
// BM=128, BK=16, double-buffered smem (48 KB), 256 threads, FFMA2 math,
// bf16x2 epilogue. Shared by the standalone and fused kernels.
template <int BN>
__device__ __forceinline__ void gemm_body(const float* __restrict__ A,
                                          const float* __restrict__ B,
                                          __nv_bfloat16* __restrict__ C,
                                          int M, int block) {
    constexpr int K = 128, BM = 128, BK = 16;
    constexpr int TM = 8, TN = BN / 16, TN2 = TN / 2;
    constexpr int NSLAB = K / BK;                 // 8
    constexpr int A_IT = (BM * BK / 4) / 256;     // 2
    constexpr int B_IT = (BK * BN / 4) / 256;     // 2 (BN=128) / 1 (BN=64)

    __shared__ unsigned long long As2[2][BK][BM]; // 2 x 16 KB, {a,a} pairs
    __shared__ float Bs[2][BK][BN];               // 2 x 8/4 KB

    const int tid = threadIdx.x;
    const int m0  = block * BM;
    const int tx  = tid % 16;
    const int ty  = tid / 16;
    const int mm  = ty * TM;
    const int nn  = tx * TN;

    unsigned long long acc2[TM][TN2];
#pragma unroll
    for (int i = 0; i < TM; i++)
#pragma unroll
        for (int j = 0; j < TN2; j++) acc2[i][j] = 0ull;

    const float4* A4 = reinterpret_cast<const float4*>(A);
    const float4* B4 = reinterpret_cast<const float4*>(B);

    float4 areg[A_IT], breg[B_IT];

    auto load_global = [&](int s) {
#pragma unroll
        for (int it = 0; it < A_IT; it++) {
            int f  = tid + it * 256;
            int m  = f & (BM - 1);
            int kq = f >> 7;                       // 0..BK/4-1
            int gm = m0 + m;
            areg[it] = (gm < M) ? A4[gm * (K / 4) + (s * BK) / 4 + kq]
                                : make_float4(0.f, 0.f, 0.f, 0.f);
        }
#pragma unroll
        for (int it = 0; it < B_IT; it++) {
            int f = tid + it * 256;
            breg[it] = B4[(s * BK) * (BN / 4) + f];
        }
    };
    auto store_smem = [&](int buf) {
#pragma unroll
        for (int it = 0; it < A_IT; it++) {
            int f  = tid + it * 256;
            int m  = f & (BM - 1);
            int k  = (f >> 7) * 4;
            As2[buf][k + 0][m] = dup2(areg[it].x);
            As2[buf][k + 1][m] = dup2(areg[it].y);
            As2[buf][k + 2][m] = dup2(areg[it].z);
            As2[buf][k + 3][m] = dup2(areg[it].w);
        }
#pragma unroll
        for (int it = 0; it < B_IT; it++) {
            int f = tid + it * 256;
            reinterpret_cast<float4*>(&Bs[buf][0][0])[f] = breg[it];
        }
    };
    auto compute = [&](int buf) {
#pragma unroll
        for (int k = 0; k < BK; k++) {
            unsigned long long a2[TM];
#pragma unroll
            for (int i2 = 0; i2 < TM / 2; i2++) {
                ulonglong2 av = *reinterpret_cast<const ulonglong2*>(&As2[buf][k][mm + i2 * 2]);
                a2[i2 * 2 + 0] = av.x;
                a2[i2 * 2 + 1] = av.y;
            }
            unsigned long long b2[TN2];
#pragma unroll
            for (int j4 = 0; j4 < TN2 / 2; j4++) {
                ulonglong2 bv = *reinterpret_cast<const ulonglong2*>(&Bs[buf][k][nn + j4 * 4]);
                b2[j4 * 2 + 0] = bv.x;
                b2[j4 * 2 + 1] = bv.y;
            }
#pragma unroll
            for (int i = 0; i < TM; i++)
#pragma unroll
                for (int j = 0; j < TN2; j++) ffma2(acc2[i][j], a2[i], b2[j]);
        }
    };

    load_global(0);
    store_smem(0);
    __syncthreads();

    for (int s = 0; s < NSLAB; s++) {
        int cur = s & 1;
        bool has_next = (s + 1) < NSLAB;
        if (has_next) load_global(s + 1);   // LDG latency hidden by compute
        compute(cur);
        if (has_next) store_smem(cur ^ 1);
        __syncthreads();
    }

    // epilogue: pack each f32 pair -> bf16x2, vector store
#pragma unroll
    for (int i = 0; i < TM; i++) {
        int row = m0 + mm + i;
        if (row < M) {
            unsigned r32[TN2];
#pragma unroll
            for (int j = 0; j < TN2; j++) r32[j] = cvt_bf2(acc2[i][j]);
            unsigned* outp = reinterpret_cast<unsigned*>(C + row * BN + nn);
            if constexpr (TN2 == 4) {
                uint4 o = make_uint4(r32[0], r32[1], r32[2], r32[3]);
                *reinterpret_cast<uint4*>(outp) = o;
            } else {
                uint2 o = make_uint2(r32[0], r32[1]);
                *reinterpret_cast<uint2*>(outp) = o;
            }
        }
    }
}

template <int BN>
__global__ void __launch_bounds__(256)
gemm_kernel(const float* __restrict__ A, const float* __restrict__ B,
            __nv_bfloat16* __restrict__ C, int M) {
    gemm_body<BN>(A, B, C, M, blockIdx.x);
}

// ---------------- fused: gemm0 tiles + edge histogram in one grid ----------------
__global__ void __launch_bounds__(256)
gemm0_hist_kernel(const float* __restrict__ A, const float* __restrict__ B,
                  __nv_bfloat16* __restrict__ C,
                  const int* __restrict__ dst) {
    if (blockIdx.x >= NB_GEMM_C) {
        // histogram part (runs concurrently with gemm0 tiles)
        int e = (blockIdx.x - NB_GEMM_C) * 256 + (int)threadIdx.x;
        if (e < N_EDGES) atomicAdd(&g_cursor[dst[e]], 1);
        if (blockIdx.x == NB_GEMM_C && threadIdx.x == 0) g_scan_done = 0;
        return;
    }
    gemm_body<128>(A, B, C, N_NODES, blockIdx.x);
}

// ---------------- scan (single kernel, last-block-ticket top scan) ----------------
// Output: g_rowptr = chunk-local exclusive prefix (per 512-node chunk),
//         g_blocksum = exclusive chunk offsets. Consumers add them together.
__global__ void scan_blocks_kernel() {
    __shared__ int sdata[512];
    __shared__ int flag;
    __shared__ int tops[128];
    const int tid = threadIdx.x;
    int i = blockIdx.x * 512 + tid;
    int v = (i < N_NODES) ? g_cursor[i] : 0;
    if (i < N_NODES) g_cursor[i] = 0;         // re-zero for scatter pass
    sdata[tid] = v;
    __syncthreads();
#pragma unroll
    for (int off = 1; off < 512; off <<= 1) {
        int t = (tid >= off) ? sdata[tid - off] : 0;
        __syncthreads();
        sdata[tid] += t;
        __syncthreads();
    }
    if (i <= N_NODES) g_rowptr[i] = sdata[tid] - v;   // chunk-local exclusive
    if (tid == 511) {
        g_blocksum[blockIdx.x] = sdata[511];          // chunk total
        __threadfence();                              // publish before ticket
        int t = atomicAdd(&g_scan_done, 1);
        flag = (t == NBLK_SCAN - 1) ? 1 : 0;
    }
    __syncthreads();
    if (flag) {                                       // last block: top scan
        int tv = 0;
        if (tid < 128) {
            tv = (tid < NBLK_SCAN) ? *((volatile int*)&g_blocksum[tid]) : 0;
            tops[tid] = tv;
        }
        __syncthreads();
        for (int off = 1; off < 128; off <<= 1) {
            int t2 = 0;
            if (tid < 128 && tid >= off) t2 = tops[tid - off];
            __syncthreads();
            if (tid < 128) tops[tid] += t2;
            __syncthreads();
        }
        if (tid < NBLK_SCAN) g_blocksum[tid] = tops[tid] - tv;  // exclusive
    }
}

__global__ void scatter_kernel(const int* __restrict__ src,
                               const int* __restrict__ dst,
                               const float* __restrict__ w) {
    int e = blockIdx.x * blockDim.x + threadIdx.x;
    if (e < N_EDGES) {
        int d = dst[e];
        int pos = g_rowptr[d] + g_blocksum[d >> 9] + atomicAdd(&g_cursor[d], 1);
        reinterpret_cast<int2*>(g_csr_ew)[pos] =
            make_int2(src[e], __float_as_int(w[e]));
    }
}

// ---------------- SpMM (CSR-by-dst, bf16 gather, packed edges) ----------------
// one warp per destination node; lane owns D/32 consecutive channels.
template <int D, bool RELU>
__global__ void spmm_kernel(const __nv_bfloat16* __restrict__ sup,
                            const float* __restrict__ bias,
                            float* __restrict__ out) {
    int gw = (blockIdx.x * blockDim.x + threadIdx.x) >> 5;
    if (gw >= N_NODES) return;
    int lane = threadIdx.x & 31;
    int s = g_rowptr[gw]     + g_blocksum[gw >> 9];
    int e = g_rowptr[gw + 1] + g_blocksum[(gw + 1) >> 9];

    const int4* ew4 = reinterpret_cast<const int4*>(g_csr_ew);  // 2 edges each
    const int2* ew2 = reinterpret_cast<const int2*>(g_csr_ew);  // 1 edge each

    if constexpr (D == 128) {
        const uint2* supv = reinterpret_cast<const uint2*>(sup);  // 32 uint2/row
        float4 acc = make_float4(0.f, 0.f, 0.f, 0.f);
        int i = s;

        auto edge = [&](int sn, float wn) {
            uint2 v = supv[sn * 32 + lane];
            float2 p;
            p = bf2f(v.x); acc.x += wn * p.x; acc.y += wn * p.y;
            p = bf2f(v.y); acc.z += wn * p.x; acc.w += wn * p.y;
        };

        if (i < e && (i & 1)) {               // align to int4 boundary
            int2 p = ew2[i];
            edge(p.x, __int_as_float(p.y));
            i++;
        }
        for (; i + 3 < e; i += 4) {           // 4 edges: 2 LDG.128 + 4 gathers
            int4 pa = ew4[i >> 1];
            int4 pb = ew4[(i >> 1) + 1];
            uint2 v0 = supv[pa.x * 32 + lane];
            uint2 v1 = supv[pa.z * 32 + lane];
            uint2 v2 = supv[pb.x * 32 + lane];
            uint2 v3 = supv[pb.z * 32 + lane];
            float w0 = __int_as_float(pa.y), w1 = __int_as_float(pa.w);
            float w2 = __int_as_float(pb.y), w3 = __int_as_float(pb.w);
            float2 p;
            p = bf2f(v0.x); acc.x += w0 * p.x; acc.y += w0 * p.y;
            p = bf2f(v0.y); acc.z += w0 * p.x; acc.w += w0 * p.y;
            p = bf2f(v1.x); acc.x += w1 * p.x; acc.y += w1 * p.y;
            p = bf2f(v1.y); acc.z += w1 * p.x; acc.w += w1 * p.y;
            p = bf2f(v2.x); acc.x += w2 * p.x; acc.y += w2 * p.y;
            p = bf2f(v2.y); acc.z += w2 * p.x; acc.w += w2 * p.y;
            p = bf2f(v3.x); acc.x += w3 * p.x; acc.y += w3 * p.y;
            p = bf2f(v3.y); acc.z += w3 * p.x; acc.w += w3 * p.y;
        }
        for (; i + 1 < e; i += 2) {
            int4 pa = ew4[i >> 1];
            edge(pa.x, __int_as_float(pa.y));
            edge(pa.z, __int_as_float(pa.w));
        }
        if (i < e) {
            int2 p = ew2[i];
            edge(p.x, __int_as_float(p.y));
        }

        float4 b = reinterpret_cast<const float4*>(bias)[lane];
        acc.x += b.x; acc.y += b.y; acc.z += b.z; acc.w += b.w;
        if (RELU) {
            acc.x = fmaxf(acc.x, 0.f); acc.y = fmaxf(acc.y, 0.f);
            acc.z = fmaxf(acc.z, 0.f); acc.w = fmaxf(acc.w, 0.f);
        }
        reinterpret_cast<float4*>(out)[gw * 32 + lane] = acc;
    } else {  // D == 64
        const unsigned* supv = reinterpret_cast<const unsigned*>(sup);  // 32 u32/row
        float2 acc = make_float2(0.f, 0.f);
        int i = s;

        auto edge = [&](int sn, float wn) {
            float2 p = bf2f(supv[sn * 32 + lane]);
            acc.x += wn * p.x; acc.y += wn * p.y;
        };

        if (i < e && (i & 1)) {
            int2 p = ew2[i];
            edge(p.x, __int_as_float(p.y));
            i++;
        }
        for (; i + 3 < e; i += 4) {
            int4 pa = ew4[i >> 1];
            int4 pb = ew4[(i >> 1) + 1];
            unsigned v0 = supv[pa.x * 32 + lane];
            unsigned v1 = supv[pa.z * 32 + lane];
            unsigned v2 = supv[pb.x * 32 + lane];
            unsigned v3 = supv[pb.z * 32 + lane];
            float w0 = __int_as_float(pa.y), w1 = __int_as_float(pa.w);
            float w2 = __int_as_float(pb.y), w3 = __int_as_float(pb.w);
            float2 p;
            p = bf2f(v0); acc.x += w0 * p.x; acc.y += w0 * p.y;
            p = bf2f(v1); acc.x += w1 * p.x; acc.y += w1 * p.y;
            p = bf2f(v2); acc.x += w2 * p.x; acc.y += w2 * p.y;
            p = bf2f(v3); acc.x += w3 * p.x; acc.y += w3 * p.y;
        }
        for (; i + 1 < e; i += 2) {
            int4 pa = ew4[i >> 1];
            edge(pa.x, __int_as_float(pa.y));
            edge(pa.z, __int_as_float(pa.w));
        }
        if (i < e) {
            int2 p = ew2[i];
            edge(p.x, __int_as_float(p.y));
        }

        float2 b = reinterpret_cast<const float2*>(bias)[lane];
        acc.x += b.x; acc.y += b.y;
        if (RELU) { acc.x = fmaxf(acc.x, 0.f); acc.y = fmaxf(acc.y, 0.f); }
        reinterpret_cast<float2*>(out)[gw * 32 + lane] = acc;
    }
}

// ---------------- launch (single stream) ----------------
extern "C" void kernel_launch(void* const* d_in, const int* in_sizes, int n_in,
                              void* d_out, int out_size) {
    const float* x        = (const float*)d_in[0];
    const int*   edge_src = (const int*)  d_in[1];
    const int*   edge_dst = (const int*)  d_in[2];
    const float* edge_w   = (const float*)d_in[3];
    const float* W0 = (const float*)d_in[4];  const float* b0 = (const float*)d_in[5];
    const float* W1 = (const float*)d_in[6];  const float* b1 = (const float*)d_in[7];
    const float* W2 = (const float*)d_in[8];  const float* b2 = (const float*)d_in[9];
    const float* W3 = (const float*)d_in[10]; const float* b3 = (const float*)d_in[11];
    float* out = (float*)d_out;

    __nv_bfloat16* support; cudaGetSymbolAddress((void**)&support, g_support);
    float* h;               cudaGetSymbolAddress((void**)&h, g_h);
    int*   cursor;          cudaGetSymbolAddress((void**)&cursor, g_cursor);

    const int NB_SPMM = (N_NODES + 7) / 8;      // 8 warps/block

    // cursor must be zero before the fused histogram (scan re-zeroes it for
    // scatter; this memset covers the very first call and is cheap after).
    cudaMemsetAsync(cursor, 0, N_NODES * sizeof(int), 0);

    // layer-0 GEMM fused with edge histogram (independent work, one grid)
    gemm0_hist_kernel<<<NB_GEMM_C + NB_EDGE_C, 256>>>(x, W0, support, edge_dst);

    // one-kernel scan (local scans + last-block top scan)
    scan_blocks_kernel<<<NBLK_SCAN, 512>>>();
    scatter_kernel<<<NB_EDGE_C, 256>>>(edge_src, edge_dst, edge_w);

    // layer 0 aggregate
    spmm_kernel<128, true><<<NB_SPMM, 256>>>(support, b0, h);
    // layer 1
    gemm_kernel<128><<<NB_GEMM_C, 256>>>(h, W1, support, N_NODES);
    spmm_kernel<128, true><<<NB_SPMM, 256>>>(support, b1, h);
    // layer 2
    gemm_kernel<128><<<NB_GEMM_C, 256>>>(h, W2, support, N_NODES);
    spmm_kernel<128, true><<<NB_SPMM, 256>>>(support, b2, h);
    // layer 3 (d=64, no relu) -> d_out
    gemm_kernel<64><<<NB_GEMM_C, 256>>>(h, W3, support, N_NODES);
    spmm_kernel<64, false><<<NB_SPMM, 256>>>(support, b3, out);
}